// round 13
// baseline (speedup 1.0000x reference)
#include <cuda_runtime.h>
#include <cuda_fp16.h>
#include <cstdint>
#include <cstddef>
#include <cstring>

// Problem dims (fixed by setup_inputs)
#define NROWS 8192
#define DDIM  512

// GEMM tiling
#define TILE_M 128
#define TILE_N 256
#define TILE_K 64           // 64 f16 = 128B row = SW128 atom
#define STAGES 3
#define NTHREADS 512        // 16 warps, 4x4 warp grid, warp tile 32x64

#define STAGE_A_BYTES (TILE_M * 128)          // 16384
#define STAGE_B_BYTES (TILE_N * 128)          // 32768
#define STAGE_BYTES   (STAGE_A_BYTES + STAGE_B_BYTES)  // 49152
#define SMEM_TOTAL    (STAGES * STAGE_BYTES)  // 147456

// Scratch (device globals: allocation-free per harness rules)
__device__ __align__(256) __half g_ba[(size_t)NROWS * DDIM];   // binarized x {0,1}
__device__ __align__(256) __half g_bw[(size_t)DDIM * DDIM];    // sign(W) {-1,0,1}
__device__ __align__(256) __half g_xwT[(size_t)DDIM * NROWS];  // xw^T [n][m], K-major B for GEMM2

// ---------------- helpers ----------------
__device__ __forceinline__ uint32_t h2_bits(__half2 h) {
    uint32_t u; memcpy(&u, &h, sizeof(u)); return u;
}
__device__ __forceinline__ uint32_t smem_u32(const void* p) {
    uint32_t a;
    asm("{ .reg .u64 t; cvta.to.shared.u64 t, %1; cvt.u32.u64 %0, t; }" : "=r"(a) : "l"(p));
    return a;
}
__device__ __forceinline__ uint32_t sw128(uint32_t off) {
    return off ^ ((off >> 3) & 0x70);
}
__device__ __forceinline__ void cp_async16(uint32_t s, const void* g) {
    asm volatile("cp.async.cg.shared.global [%0], [%1], 16;" :: "r"(s), "l"(g) : "memory");
}
__device__ __forceinline__ void cp_commit() { asm volatile("cp.async.commit_group;" ::: "memory"); }
template <int N>
__device__ __forceinline__ void cp_wait() { asm volatile("cp.async.wait_group %0;" :: "n"(N) : "memory"); }

__device__ __forceinline__ void ldm_x4(uint32_t* r, uint32_t addr) {
    asm volatile("ldmatrix.sync.aligned.m8n8.x4.shared.b16 {%0,%1,%2,%3}, [%4];"
                 : "=r"(r[0]), "=r"(r[1]), "=r"(r[2]), "=r"(r[3]) : "r"(addr));
}
__device__ __forceinline__ void mma16816(float* d, const uint32_t* a, const uint32_t* b) {
    asm volatile("mma.sync.aligned.m16n8k16.row.col.f32.f16.f16.f32 "
                 "{%0,%1,%2,%3}, {%4,%5,%6,%7}, {%8,%9}, {%0,%1,%2,%3};"
                 : "+f"(d[0]), "+f"(d[1]), "+f"(d[2]), "+f"(d[3])
                 : "r"(a[0]), "r"(a[1]), "r"(a[2]), "r"(a[3]), "r"(b[0]), "r"(b[1]));
}

// ---------------- prep kernel ----------------
__global__ void prep_bin_kernel(const float* __restrict__ x, const float* __restrict__ w) {
    const int stride = gridDim.x * blockDim.x;
    int i = blockIdx.x * blockDim.x + threadIdx.x;
    for (int j = i; j < NROWS * DDIM; j += stride)
        g_ba[j] = __float2half(x[j] > 0.0f ? 1.0f : 0.0f);
    for (int j = i; j < DDIM * DDIM; j += stride) {
        float v = w[j];
        g_bw[j] = __float2half(v > 0.0f ? 1.0f : (v < 0.0f ? -1.0f : 0.0f));
    }
}

// ---------------- GEMM kernel (mma.sync, base ISA) ----------------
// C[M,N] = A[M,K] * B[N,K]^T, fp16 in / fp32 accum.
// G2=false: A=g_ba (K=512) cp.async, B=g_bw,  epilogue -> g_xwT (fp16 transposed)
// G2=true : A=support f32 (K=8192) fused-convert LDG->cvt->STS, B=g_xwT,
//           epilogue -> out (f32, relu)
template <bool G2>
__global__ void __launch_bounds__(NTHREADS, 1)
gemm_kernel(const float* __restrict__ Af32, float* __restrict__ out) {
    extern __shared__ __align__(1024) char smem[];
    const uint32_t sb = smem_u32(smem);
    const int tid  = threadIdx.x;
    const int l    = tid & 31;
    const int w    = tid >> 5;
    const int wm   = w >> 2;          // 0-3: M position
    const int wn   = w & 3;           // 0-3: N position
    const int KT   = (G2 ? NROWS : DDIM) / TILE_K;
    const int ldk  = G2 ? NROWS : DDIM;
    const __half* __restrict__ B = G2 ? g_xwT : g_bw;
    const int m0 = blockIdx.y * TILE_M;
    const int n0 = blockIdx.x * TILE_N;

    auto load_tile = [&](int kt, int s) {
        char* stA = smem + s * STAGE_BYTES;
        const uint32_t sA = sb + s * STAGE_BYTES;
        const uint32_t sB = sA + STAGE_A_BYTES;
        if constexpr (G2) {
            // A: f32 -> f16 fused convert. 1024 16B-dst segs, 2 per thread.
            const float* gA = Af32 + (size_t)m0 * NROWS + kt * TILE_K;
            #pragma unroll
            for (int q = tid; q < TILE_M * 8; q += NTHREADS) {
                int r = q >> 3, seg = q & 7;
                const float4* p4 = reinterpret_cast<const float4*>(
                    gA + (size_t)r * NROWS + seg * 8);
                float4 v0 = __ldg(p4);
                float4 v1 = __ldg(p4 + 1);
                uint4 h;
                h.x = h2_bits(__floats2half2_rn(v0.x, v0.y));
                h.y = h2_bits(__floats2half2_rn(v0.z, v0.w));
                h.z = h2_bits(__floats2half2_rn(v1.x, v1.y));
                h.w = h2_bits(__floats2half2_rn(v1.z, v1.w));
                *reinterpret_cast<uint4*>(stA + sw128((uint32_t)(r * 128 + seg * 16))) = h;
            }
        } else {
            const __half* gA = g_ba + (size_t)m0 * ldk + kt * TILE_K;
            #pragma unroll
            for (int q = tid; q < TILE_M * 8; q += NTHREADS) {
                int r = q >> 3, seg = q & 7;
                cp_async16(sA + sw128((uint32_t)(r * 128 + seg * 16)),
                           gA + (size_t)r * ldk + seg * 8);
            }
        }
        const __half* gB = B + (size_t)n0 * ldk + kt * TILE_K;
        #pragma unroll
        for (int q = tid; q < TILE_N * 8; q += NTHREADS) {
            int r = q >> 3, seg = q & 7;
            cp_async16(sB + sw128((uint32_t)(r * 128 + seg * 16)),
                       gB + (size_t)r * ldk + seg * 8);
        }
    };

    float acc[2][8][4];
    #pragma unroll
    for (int i = 0; i < 2; i++)
        #pragma unroll
        for (int j = 0; j < 8; j++)
            #pragma unroll
            for (int c = 0; c < 4; c++) acc[i][j][c] = 0.0f;

    // Prologue
    load_tile(0, 0); cp_commit();
    load_tile(1, 1); cp_commit();

    const int g = l >> 3, r8 = l & 7;

    for (int kt = 0; kt < KT; kt++) {
        cp_wait<1>();        // stage kt's cp.async group complete (this thread)
        __syncthreads();     // all threads' cp.async + STS for stage kt visible
        if (kt + 2 < KT) load_tile(kt + 2, (kt + 2) % STAGES);
        cp_commit();         // commit (possibly empty) to keep group accounting uniform

        const int s = kt % STAGES;
        const uint32_t sA = sb + s * STAGE_BYTES;
        const uint32_t sB = sA + STAGE_A_BYTES;

        #pragma unroll
        for (int ks = 0; ks < 4; ks++) {
            uint32_t a[2][4];
            #pragma unroll
            for (int mt = 0; mt < 2; mt++) {
                int row = wm * 32 + mt * 16 + (g & 1) * 8 + r8;
                int kb  = ks * 32 + (g >> 1) * 16;
                ldm_x4(a[mt], sA + sw128((uint32_t)(row * 128 + kb)));
            }
            uint32_t b[8][2];
            #pragma unroll
            for (int bt = 0; bt < 4; bt++) {
                int row = wn * 64 + bt * 16 + (g >> 1) * 8 + r8;
                int kb  = ks * 32 + (g & 1) * 16;
                uint32_t t[4];
                ldm_x4(t, sB + sw128((uint32_t)(row * 128 + kb)));
                b[bt * 2][0] = t[0]; b[bt * 2][1] = t[1];
                b[bt * 2 + 1][0] = t[2]; b[bt * 2 + 1][1] = t[3];
            }
            #pragma unroll
            for (int mt = 0; mt < 2; mt++)
                #pragma unroll
                for (int nt = 0; nt < 8; nt++)
                    mma16816(acc[mt][nt], a[mt], b[nt]);
        }
    }

    // Epilogue. c0,c1 = (row, col..col+1); c2,c3 = (row+8, col..col+1)
    #pragma unroll
    for (int mt = 0; mt < 2; mt++) {
        #pragma unroll
        for (int nt = 0; nt < 8; nt++) {
            int row = m0 + wm * 32 + mt * 16 + (l >> 2);
            int col = n0 + wn * 64 + nt * 8 + (l & 3) * 2;
            float* c = acc[mt][nt];
            if (G2) {
                float2 v0 = make_float2(fmaxf(c[0], 0.0f), fmaxf(c[1], 0.0f));
                float2 v1 = make_float2(fmaxf(c[2], 0.0f), fmaxf(c[3], 0.0f));
                *reinterpret_cast<float2*>(out + (size_t)row * DDIM + col) = v0;
                *reinterpret_cast<float2*>(out + (size_t)(row + 8) * DDIM + col) = v1;
            } else {
                // transposed fp16 store: g_xwT[n][m] (values are exact small ints)
                g_xwT[(size_t)col * NROWS + row]           = __float2half(c[0]);
                g_xwT[(size_t)(col + 1) * NROWS + row]     = __float2half(c[1]);
                g_xwT[(size_t)col * NROWS + row + 8]       = __float2half(c[2]);
                g_xwT[(size_t)(col + 1) * NROWS + row + 8] = __float2half(c[3]);
            }
        }
    }
}

// ---------------- launch ----------------
extern "C" void kernel_launch(void* const* d_in, const int* in_sizes, int n_in,
                              void* d_out, int out_size) {
    const float* x = nullptr;        // 8192*512
    const float* support = nullptr;  // 8192*8192
    const float* w = nullptr;        // 512*512
    for (int i = 0; i < n_in; i++) {
        if (in_sizes[i] == NROWS * DDIM)        x = (const float*)d_in[i];
        else if (in_sizes[i] == DDIM * DDIM)    w = (const float*)d_in[i];
        else                                    support = (const float*)d_in[i];
    }
    float* out = (float*)d_out;

    cudaFuncSetAttribute(gemm_kernel<false>, cudaFuncAttributeMaxDynamicSharedMemorySize, SMEM_TOTAL);
    cudaFuncSetAttribute(gemm_kernel<true>,  cudaFuncAttributeMaxDynamicSharedMemorySize, SMEM_TOTAL);

    prep_bin_kernel<<<2048, 256>>>(x, w);

    dim3 grid(DDIM / TILE_N, NROWS / TILE_M);  // (2, 64)
    gemm_kernel<false><<<grid, NTHREADS, SMEM_TOTAL>>>(nullptr, nullptr);
    gemm_kernel<true ><<<grid, NTHREADS, SMEM_TOTAL>>>(support, out);
}

// round 17
// speedup vs baseline: 1.2636x; 1.2636x over previous
#include <cuda_runtime.h>
#include <cuda_fp16.h>
#include <cstdint>
#include <cstddef>
#include <cstring>

// Problem dims (fixed by setup_inputs)
#define NROWS 8192
#define DDIM  512

// GEMM tiling
#define TILE_M 128
#define TILE_N 256
#define TILE_K 64           // 64 f16 = 128B row = SW128 atom
#define STAGES 3
#define NTHREADS 512        // 16 warps, 4x4 warp grid, warp tile 32x64

#define STAGE_A_BYTES (TILE_M * 128)          // 16384
#define STAGE_B_BYTES (TILE_N * 128)          // 32768
#define STAGE_BYTES   (STAGE_A_BYTES + STAGE_B_BYTES)  // 49152
#define SMEM_TOTAL    (STAGES * STAGE_BYTES)  // 147456

// Scratch (device globals: allocation-free per harness rules)
__device__ __align__(256) __half g_ba[(size_t)NROWS * DDIM];   // binarized x {0,1}
__device__ __align__(256) __half g_bw[(size_t)DDIM * DDIM];    // sign(W) {-1,0,1}
__device__ __align__(256) __half g_xwT[(size_t)DDIM * NROWS];  // xw^T [n][m], K-major B for GEMM2

// ---------------- helpers ----------------
__device__ __forceinline__ uint32_t h2_bits(__half2 h) {
    uint32_t u; memcpy(&u, &h, sizeof(u)); return u;
}
__device__ __forceinline__ uint32_t smem_u32(const void* p) {
    uint32_t a;
    asm("{ .reg .u64 t; cvta.to.shared.u64 t, %1; cvt.u32.u64 %0, t; }" : "=r"(a) : "l"(p));
    return a;
}
__device__ __forceinline__ uint32_t sw128(uint32_t off) {
    return off ^ ((off >> 3) & 0x70);
}
__device__ __forceinline__ void cp_async16(uint32_t s, const void* g) {
    asm volatile("cp.async.cg.shared.global [%0], [%1], 16;" :: "r"(s), "l"(g) : "memory");
}
__device__ __forceinline__ void cp_commit() { asm volatile("cp.async.commit_group;" ::: "memory"); }
template <int N>
__device__ __forceinline__ void cp_wait() { asm volatile("cp.async.wait_group %0;" :: "n"(N) : "memory"); }

__device__ __forceinline__ void ldm_x4(uint32_t* r, uint32_t addr) {
    asm volatile("ldmatrix.sync.aligned.m8n8.x4.shared.b16 {%0,%1,%2,%3}, [%4];"
                 : "=r"(r[0]), "=r"(r[1]), "=r"(r[2]), "=r"(r[3]) : "r"(addr));
}
__device__ __forceinline__ void mma16816(float* d, const uint32_t* a, const uint32_t* b) {
    asm volatile("mma.sync.aligned.m16n8k16.row.col.f32.f16.f16.f32 "
                 "{%0,%1,%2,%3}, {%4,%5,%6,%7}, {%8,%9}, {%0,%1,%2,%3};"
                 : "+f"(d[0]), "+f"(d[1]), "+f"(d[2]), "+f"(d[3])
                 : "r"(a[0]), "r"(a[1]), "r"(a[2]), "r"(a[3]), "r"(b[0]), "r"(b[1]));
}

// ---------------- prep kernel (vectorized) ----------------
__global__ void prep_bin_kernel(const float4* __restrict__ x4, const float4* __restrict__ w4) {
    const int stride = gridDim.x * blockDim.x;
    int i = blockIdx.x * blockDim.x + threadIdx.x;
    uint2* ba2 = reinterpret_cast<uint2*>(g_ba);
    uint2* bw2 = reinterpret_cast<uint2*>(g_bw);
    const int nx = NROWS * DDIM / 4;
    for (int j = i; j < nx; j += stride) {
        float4 v = x4[j];
        uint2 o;
        o.x = h2_bits(__floats2half2_rn(v.x > 0.0f ? 1.0f : 0.0f, v.y > 0.0f ? 1.0f : 0.0f));
        o.y = h2_bits(__floats2half2_rn(v.z > 0.0f ? 1.0f : 0.0f, v.w > 0.0f ? 1.0f : 0.0f));
        ba2[j] = o;
    }
    const int nw = DDIM * DDIM / 4;
    for (int j = i; j < nw; j += stride) {
        float4 v = w4[j];
        uint2 o;
        o.x = h2_bits(__floats2half2_rn(
            v.x > 0.0f ? 1.0f : (v.x < 0.0f ? -1.0f : 0.0f),
            v.y > 0.0f ? 1.0f : (v.y < 0.0f ? -1.0f : 0.0f)));
        o.y = h2_bits(__floats2half2_rn(
            v.z > 0.0f ? 1.0f : (v.z < 0.0f ? -1.0f : 0.0f),
            v.w > 0.0f ? 1.0f : (v.w < 0.0f ? -1.0f : 0.0f)));
        bw2[j] = o;
    }
}

// ---------------- GEMM kernel (mma.sync, base ISA) ----------------
// C[M,N] = A[M,K] * B[N,K]^T, fp16 in / fp32 accum.
// G2=false: A=g_ba (K=512) cp.async, B=g_bw,  epilogue -> g_xwT (fp16 transposed)
// G2=true : A=support f32 (K=8192), REGISTER-STAGED fused convert:
//           LDG (pre-barrier, overlaps mma) ... mma ... cvt+STS (post-mma).
//           B=g_xwT via cp.async. Epilogue -> out (f32, relu).
template <bool G2>
__global__ void __launch_bounds__(NTHREADS, 1)
gemm_kernel(const float* __restrict__ Af32, float* __restrict__ out) {
    extern __shared__ __align__(1024) char smem[];
    const uint32_t sb = smem_u32(smem);
    const int tid  = threadIdx.x;
    const int l    = tid & 31;
    const int w    = tid >> 5;
    const int wm   = w >> 2;          // 0-3: M position
    const int wn   = w & 3;           // 0-3: N position
    const int KT   = (G2 ? NROWS : DDIM) / TILE_K;
    const int ldk  = G2 ? NROWS : DDIM;
    const __half* __restrict__ B = G2 ? g_xwT : g_bw;
    const int m0 = blockIdx.y * TILE_M;
    const int n0 = blockIdx.x * TILE_N;

    // This thread's two A segments (q = tid, tid + 512): row/seg decomposition
    const int ar0 = tid >> 3,           as0 = tid & 7;
    const int ar1 = (tid + 512) >> 3,   as1 = (tid + 512) & 7;

    auto load_B = [&](int kt, int s) {
        const uint32_t sB = sb + s * STAGE_BYTES + STAGE_A_BYTES;
        const __half* gB = B + (size_t)n0 * ldk + kt * TILE_K;
        #pragma unroll
        for (int q = tid; q < TILE_N * 8; q += NTHREADS) {
            int r = q >> 3, seg = q & 7;
            cp_async16(sB + sw128((uint32_t)(r * 128 + seg * 16)),
                       gB + (size_t)r * ldk + seg * 8);
        }
    };
    auto load_A_direct = [&](int kt, int s) {   // prologue only (latency exposed once)
        char* stA = smem + s * STAGE_BYTES;
        if constexpr (G2) {
            const float* gA = Af32 + (size_t)m0 * NROWS + kt * TILE_K;
            #pragma unroll
            for (int q = tid; q < TILE_M * 8; q += NTHREADS) {
                int r = q >> 3, seg = q & 7;
                const float4* p4 = reinterpret_cast<const float4*>(gA + (size_t)r * NROWS + seg * 8);
                float4 v0 = __ldg(p4), v1 = __ldg(p4 + 1);
                uint4 h;
                h.x = h2_bits(__floats2half2_rn(v0.x, v0.y));
                h.y = h2_bits(__floats2half2_rn(v0.z, v0.w));
                h.z = h2_bits(__floats2half2_rn(v1.x, v1.y));
                h.w = h2_bits(__floats2half2_rn(v1.z, v1.w));
                *reinterpret_cast<uint4*>(stA + sw128((uint32_t)(r * 128 + seg * 16))) = h;
            }
        } else {
            const uint32_t sA = sb + s * STAGE_BYTES;
            const __half* gA = g_ba + (size_t)m0 * ldk + kt * TILE_K;
            #pragma unroll
            for (int q = tid; q < TILE_M * 8; q += NTHREADS) {
                int r = q >> 3, seg = q & 7;
                cp_async16(sA + sw128((uint32_t)(r * 128 + seg * 16)),
                           gA + (size_t)r * ldk + seg * 8);
            }
        }
    };

    float acc[2][8][4];
    #pragma unroll
    for (int i = 0; i < 2; i++)
        #pragma unroll
        for (int j = 0; j < 8; j++)
            #pragma unroll
            for (int c = 0; c < 4; c++) acc[i][j][c] = 0.0f;

    // Prologue: tiles 0,1 fully loaded
    load_A_direct(0, 0); load_B(0, 0); cp_commit();
    load_A_direct(1, 1); load_B(1, 1); cp_commit();
    if constexpr (G2) { cp_wait<0>(); }  // B of tiles 0,1 in smem before loop's own accounting
    // re-commit empty groups to restore 2-group accounting
    if constexpr (G2) { cp_commit(); cp_commit(); }

    const int g = l >> 3, r8 = l & 7;

    float4 stv[4];   // register staging: seg0 {v0,v1}, seg1 {v0,v1}

    for (int kt = 0; kt < KT; kt++) {
        const int kp = kt + 2;
        const bool pre = kp < KT;

        if (G2 && pre) {
            // Issue A LDGs for tile kp now; consumed after the mma block.
            const float* gA = Af32 + (size_t)m0 * NROWS + kp * TILE_K;
            const float4* p0 = reinterpret_cast<const float4*>(gA + (size_t)ar0 * NROWS + as0 * 8);
            const float4* p1 = reinterpret_cast<const float4*>(gA + (size_t)ar1 * NROWS + as1 * 8);
            stv[0] = __ldg(p0); stv[1] = __ldg(p0 + 1);
            stv[2] = __ldg(p1); stv[3] = __ldg(p1 + 1);
        }

        cp_wait<1>();        // tile kt's B (and A when !G2) resident for this thread
        __syncthreads();     // all threads' stage-kt data visible; stage kp free of readers

        if (pre) {
            load_B(kp, kp % STAGES);
            if constexpr (!G2) load_A_direct(kp, kp % STAGES);
        }
        cp_commit();         // uniform group accounting (possibly empty)

        const int s = kt % STAGES;
        const uint32_t sA = sb + s * STAGE_BYTES;
        const uint32_t sB = sA + STAGE_A_BYTES;

        #pragma unroll
        for (int ks = 0; ks < 4; ks++) {
            uint32_t a[2][4];
            #pragma unroll
            for (int mt = 0; mt < 2; mt++) {
                int row = wm * 32 + mt * 16 + (g & 1) * 8 + r8;
                int kb  = ks * 32 + (g >> 1) * 16;
                ldm_x4(a[mt], sA + sw128((uint32_t)(row * 128 + kb)));
            }
            uint32_t b[8][2];
            #pragma unroll
            for (int bt = 0; bt < 4; bt++) {
                int row = wn * 64 + bt * 16 + (g >> 1) * 8 + r8;
                int kb  = ks * 32 + (g & 1) * 16;
                uint32_t t[4];
                ldm_x4(t, sB + sw128((uint32_t)(row * 128 + kb)));
                b[bt * 2][0] = t[0]; b[bt * 2][1] = t[1];
                b[bt * 2 + 1][0] = t[2]; b[bt * 2 + 1][1] = t[3];
            }
            #pragma unroll
            for (int mt = 0; mt < 2; mt++)
                #pragma unroll
                for (int nt = 0; nt < 8; nt++)
                    mma16816(acc[mt][nt], a[mt], b[nt]);
        }

        if (G2 && pre) {
            // Convert staged registers and store into stage kp (LDG latency long hidden).
            char* stA = smem + (kp % STAGES) * STAGE_BYTES;
            uint4 h;
            h.x = h2_bits(__floats2half2_rn(stv[0].x, stv[0].y));
            h.y = h2_bits(__floats2half2_rn(stv[0].z, stv[0].w));
            h.z = h2_bits(__floats2half2_rn(stv[1].x, stv[1].y));
            h.w = h2_bits(__floats2half2_rn(stv[1].z, stv[1].w));
            *reinterpret_cast<uint4*>(stA + sw128((uint32_t)(ar0 * 128 + as0 * 16))) = h;
            h.x = h2_bits(__floats2half2_rn(stv[2].x, stv[2].y));
            h.y = h2_bits(__floats2half2_rn(stv[2].z, stv[2].w));
            h.z = h2_bits(__floats2half2_rn(stv[3].x, stv[3].y));
            h.w = h2_bits(__floats2half2_rn(stv[3].z, stv[3].w));
            *reinterpret_cast<uint4*>(stA + sw128((uint32_t)(ar1 * 128 + as1 * 16))) = h;
        }
    }

    // Epilogue. c0,c1 = (row, col..col+1); c2,c3 = (row+8, col..col+1)
    #pragma unroll
    for (int mt = 0; mt < 2; mt++) {
        #pragma unroll
        for (int nt = 0; nt < 8; nt++) {
            int row = m0 + wm * 32 + mt * 16 + (l >> 2);
            int col = n0 + wn * 64 + nt * 8 + (l & 3) * 2;
            float* c = acc[mt][nt];
            if (G2) {
                float2 v0 = make_float2(fmaxf(c[0], 0.0f), fmaxf(c[1], 0.0f));
                float2 v1 = make_float2(fmaxf(c[2], 0.0f), fmaxf(c[3], 0.0f));
                *reinterpret_cast<float2*>(out + (size_t)row * DDIM + col) = v0;
                *reinterpret_cast<float2*>(out + (size_t)(row + 8) * DDIM + col) = v1;
            } else {
                g_xwT[(size_t)col * NROWS + row]           = __float2half(c[0]);
                g_xwT[(size_t)(col + 1) * NROWS + row]     = __float2half(c[1]);
                g_xwT[(size_t)col * NROWS + row + 8]       = __float2half(c[2]);
                g_xwT[(size_t)(col + 1) * NROWS + row + 8] = __float2half(c[3]);
            }
        }
    }
}

// ---------------- launch ----------------
extern "C" void kernel_launch(void* const* d_in, const int* in_sizes, int n_in,
                              void* d_out, int out_size) {
    const float* x = nullptr;        // 8192*512
    const float* support = nullptr;  // 8192*8192
    const float* w = nullptr;        // 512*512
    for (int i = 0; i < n_in; i++) {
        if (in_sizes[i] == NROWS * DDIM)        x = (const float*)d_in[i];
        else if (in_sizes[i] == DDIM * DDIM)    w = (const float*)d_in[i];
        else                                    support = (const float*)d_in[i];
    }
    float* out = (float*)d_out;

    cudaFuncSetAttribute(gemm_kernel<false>, cudaFuncAttributeMaxDynamicSharedMemorySize, SMEM_TOTAL);
    cudaFuncSetAttribute(gemm_kernel<true>,  cudaFuncAttributeMaxDynamicSharedMemorySize, SMEM_TOTAL);

    prep_bin_kernel<<<1024, 256>>>((const float4*)x, (const float4*)w);

    dim3 grid(DDIM / TILE_N, NROWS / TILE_M);  // (2, 64)
    gemm_kernel<false><<<grid, NTHREADS, SMEM_TOTAL>>>(nullptr, nullptr);
    gemm_kernel<true ><<<grid, NTHREADS, SMEM_TOTAL>>>(support, out);
}